// round 12
// baseline (speedup 1.0000x reference)
#include <cuda_runtime.h>
#include <cuda_bf16.h>
#include <cuda_fp8.h>
#include <cstdint>

#define BB 8
#define CC 512
#define NN 4096
#define CQ 80
#define NP 128   // CQ padded to 128 for bf16 MMA K

// ---------------- scratch (device globals; allocation-guard safe) ----------
__device__ __nv_bfloat16  g_attnb [(size_t)BB * NN * NN];   // 256 MB bf16 P = exp(E)
__device__ unsigned char  g_attn8 [(size_t)BB * NN * NN];   // 128 MB fp8 e4m3 (row-scaled P)
__device__ unsigned char  g_v8    [(size_t)BB * CC * NN];   // 16 MB fp8 e4m3 [b][c][n]
__device__ float          g_lsum  [(size_t)BB * NN];        // row sums of dequant(P8)
__device__ unsigned       g_pmax_bits[(size_t)BB * NN];     // row max of P (float bits)
__device__ __nv_bfloat16  g_qT    [(size_t)BB * NN * NP];   // [b][n][c] padded
__device__ __nv_bfloat16  g_kT    [(size_t)BB * NN * NP];
__device__ __nv_bfloat16  g_xT    [(size_t)BB * NN * CC];   // [b][n][c]
__device__ __nv_bfloat16  g_wv    [(size_t)CC * CC];
__device__ __nv_bfloat16  g_wqp   [(size_t)NP * CC];
__device__ __nv_bfloat16  g_wkp   [(size_t)NP * CC];

// ---------------- helpers ---------------------------------------------------
__device__ __forceinline__ uint32_t smem_u32(const void* p) {
    uint32_t a;
    asm("{ .reg .u64 t; cvta.to.shared.u64 t, %1; cvt.u32.u64 %0, t; }" : "=r"(a) : "l"(p));
    return a;
}
__device__ __forceinline__ void ldsm4(uint32_t& r0, uint32_t& r1, uint32_t& r2, uint32_t& r3,
                                      uint32_t addr) {
    asm volatile("ldmatrix.sync.aligned.m8n8.x4.shared.b16 {%0,%1,%2,%3}, [%4];"
                 : "=r"(r0), "=r"(r1), "=r"(r2), "=r"(r3) : "r"(addr));
}
__device__ __forceinline__ void mma16816(float* c, uint32_t a0, uint32_t a1, uint32_t a2,
                                         uint32_t a3, uint32_t b0, uint32_t b1) {
    asm volatile("mma.sync.aligned.m16n8k16.row.col.f32.bf16.bf16.f32 "
                 "{%0,%1,%2,%3},{%4,%5,%6,%7},{%8,%9},{%0,%1,%2,%3};"
                 : "+f"(c[0]), "+f"(c[1]), "+f"(c[2]), "+f"(c[3])
                 : "r"(a0), "r"(a1), "r"(a2), "r"(a3), "r"(b0), "r"(b1));
}
__device__ __forceinline__ void mma16832fp8(float* c, uint32_t a0, uint32_t a1, uint32_t a2,
                                            uint32_t a3, uint32_t b0, uint32_t b1) {
    asm volatile("mma.sync.aligned.m16n8k32.row.col.f32.e4m3.e4m3.f32 "
                 "{%0,%1,%2,%3},{%4,%5,%6,%7},{%8,%9},{%0,%1,%2,%3};"
                 : "+f"(c[0]), "+f"(c[1]), "+f"(c[2]), "+f"(c[3])
                 : "r"(a0), "r"(a1), "r"(a2), "r"(a3), "r"(b0), "r"(b1));
}
#define CP_ASYNC16(dst, src) \
    asm volatile("cp.async.cg.shared.global [%0], [%1], 16;" :: "r"(dst), "l"(src))
#define CP_COMMIT() asm volatile("cp.async.commit_group;" ::: "memory")
#define CP_WAIT1()  asm volatile("cp.async.wait_group 1;" ::: "memory")
#define CP_WAIT0()  asm volatile("cp.async.wait_group 0;" ::: "memory")

// 128B-row swizzle; chunk in [0,8)
#define SW(r, c) ((uint32_t)(((r) * 128) + ((((c) ^ ((r) & 7))) * 16)))

// fp8 pack with dequantized feedback
__device__ __forceinline__ uint16_t pack_fp8x2(float a, float b, float& qa, float& qb) {
    __nv_fp8x2_storage_t s =
        __nv_cvt_float2_to_fp8x2(make_float2(a, b), __NV_SATFINITE, __NV_E4M3);
    __half2_raw hr = __nv_cvt_fp8x2_to_halfraw2(s, __NV_E4M3);
    float2 f = __half22float2(*(__half2*)&hr);
    qa = f.x; qb = f.y;
    return (uint16_t)s;
}

// ---------------------------------------------------------------------------
// 128x128 bf16 GEMM body, 3-stage cp.async pipeline.
// ---------------------------------------------------------------------------
template <int NK>
__device__ __forceinline__ void gemm128x128(uint32_t sb, const uint4* __restrict__ Ag,
                                            const uint4* __restrict__ Bg, int aStride,
                                            int bStride, int m0, int n0,
                                            float (&acc)[4][4][4]) {
    const int tid = threadIdx.x;
    const int lane = tid & 31, wid = tid >> 5;
    const int wm = wid >> 2, wn = wid & 3;
    const int lr = tid >> 3, lc = tid & 7;

    int a_r[4], b_r[2];
#pragma unroll
    for (int mt = 0; mt < 4; mt++) a_r[mt] = wm * 64 + mt * 16 + ((lane >> 3) & 1) * 8 + (lane & 7);
#pragma unroll
    for (int p = 0; p < 2; p++) b_r[p] = wn * 32 + p * 16 + ((lane >> 4) & 1) * 8 + (lane & 7);
    const int a_kc = (lane >> 4) & 1;
    const int b_kc = (lane >> 3) & 1;

    {
        uint32_t dA = sb, dB = sb + 16384;
#pragma unroll
        for (int p = 0; p < 4; p++) {
            int r = p * 32 + lr;
            CP_ASYNC16(dA + SW(r, lc), (const void*)(Ag + (size_t)(m0 + r) * aStride + lc));
            CP_ASYNC16(dB + SW(r, lc), (const void*)(Bg + (size_t)(n0 + r) * bStride + lc));
        }
        CP_COMMIT();
        if (NK > 1) {
            dA = sb + 32768; dB = dA + 16384;
#pragma unroll
            for (int p = 0; p < 4; p++) {
                int r = p * 32 + lr;
                CP_ASYNC16(dA + SW(r, lc), (const void*)(Ag + (size_t)(m0 + r) * aStride + 8 + lc));
                CP_ASYNC16(dB + SW(r, lc), (const void*)(Bg + (size_t)(n0 + r) * bStride + 8 + lc));
            }
            CP_COMMIT();
        }
    }

    int buf = 0, nbuf = (NK > 1) ? 1 : 0;
#pragma unroll 1
    for (int t = 0; t < NK; t++) {
        if (t + 1 < NK) CP_WAIT1(); else CP_WAIT0();
        __syncthreads();

        if (t + 2 < NK) {
            int pb = (nbuf + 1 == 3) ? 0 : nbuf + 1;
            uint32_t dA = sb + (uint32_t)pb * 32768, dB = dA + 16384;
#pragma unroll
            for (int p = 0; p < 4; p++) {
                int r = p * 32 + lr;
                CP_ASYNC16(dA + SW(r, lc),
                           (const void*)(Ag + (size_t)(m0 + r) * aStride + (t + 2) * 8 + lc));
                CP_ASYNC16(dB + SW(r, lc),
                           (const void*)(Bg + (size_t)(n0 + r) * bStride + (t + 2) * 8 + lc));
            }
            CP_COMMIT();
        }

        const uint32_t Asb = sb + (uint32_t)buf * 32768;
        const uint32_t Bsb = Asb + 16384;
#pragma unroll
        for (int ks = 0; ks < 4; ks++) {
            uint32_t aF[4][4], bF[2][4];
#pragma unroll
            for (int mt = 0; mt < 4; mt++)
                ldsm4(aF[mt][0], aF[mt][1], aF[mt][2], aF[mt][3],
                      Asb + SW(a_r[mt], ks * 2 + a_kc));
#pragma unroll
            for (int p = 0; p < 2; p++)
                ldsm4(bF[p][0], bF[p][1], bF[p][2], bF[p][3],
                      Bsb + SW(b_r[p], ks * 2 + b_kc));
#pragma unroll
            for (int mt = 0; mt < 4; mt++) {
                mma16816(acc[mt][0], aF[mt][0], aF[mt][1], aF[mt][2], aF[mt][3], bF[0][0], bF[0][1]);
                mma16816(acc[mt][1], aF[mt][0], aF[mt][1], aF[mt][2], aF[mt][3], bF[0][2], bF[0][3]);
                mma16816(acc[mt][2], aF[mt][0], aF[mt][1], aF[mt][2], aF[mt][3], bF[1][0], bF[1][1]);
                mma16816(acc[mt][3], aF[mt][0], aF[mt][1], aF[mt][2], aF[mt][3], bF[1][2], bF[1][3]);
            }
        }
        buf = (buf + 1 == 3) ? 0 : buf + 1;
        nbuf = (nbuf + 1 == 3) ? 0 : nbuf + 1;
    }
}

// ---------------------------------------------------------------------------
// convert_w (+ zero g_pmax_bits)
// ---------------------------------------------------------------------------
__global__ __launch_bounds__(256)
void convert_w_kernel(const float* __restrict__ Wv, const float* __restrict__ Wq,
                      const float* __restrict__ Wk)
{
    int idx = blockIdx.x * 256 + threadIdx.x;
    if (idx < BB * NN) g_pmax_bits[idx] = 0u;
    if (idx < CC * CC) {
        g_wv[idx] = __float2bfloat16(Wv[idx]);
    } else if (idx < CC * CC + NP * CC) {
        int i = idx - CC * CC;
        int row = i >> 9, col = i & 511;
        g_wqp[i] = __float2bfloat16(row < CQ ? Wq[row * CC + col] : 0.f);
    } else {
        int i = idx - CC * CC - NP * CC;
        int row = i >> 9, col = i & 511;
        g_wkp[i] = __float2bfloat16(row < CQ ? Wk[row * CC + col] : 0.f);
    }
}

// ---------------------------------------------------------------------------
// transpose_x: x [b][c][n] fp32 -> xT [b][n][c] bf16.
// ---------------------------------------------------------------------------
__global__ __launch_bounds__(256)
void transpose_x_kernel(const float* __restrict__ x)
{
    __shared__ __nv_bfloat16 st[128][136];
    const int b  = blockIdx.z;
    const int c0 = blockIdx.x * 128;
    const int n0 = blockIdx.y * 128;
    const int tid = threadIdx.x;

    const float* xb = x + (size_t)b * CC * NN;
#pragma unroll
    for (int k = 0; k < 8; k++) {
        int row = k * 16 + (tid >> 4);
        int col = (tid & 15) * 8;
        const float* p = xb + (size_t)(c0 + row) * NN + n0 + col;
        float4 v0 = *(const float4*)p;
        float4 v1 = *(const float4*)(p + 4);
        st[col + 0][row] = __float2bfloat16(v0.x);
        st[col + 1][row] = __float2bfloat16(v0.y);
        st[col + 2][row] = __float2bfloat16(v0.z);
        st[col + 3][row] = __float2bfloat16(v0.w);
        st[col + 4][row] = __float2bfloat16(v1.x);
        st[col + 5][row] = __float2bfloat16(v1.y);
        st[col + 6][row] = __float2bfloat16(v1.z);
        st[col + 7][row] = __float2bfloat16(v1.w);
    }
    __syncthreads();

    uint4* xT = (uint4*)(g_xT + (size_t)b * NN * CC);
#pragma unroll
    for (int k = 0; k < 8; k++) {
        int idx = k * 256 + tid;
        int r = idx >> 4, j = idx & 15;
        uint4 val = *(uint4*)&st[r][j * 8];
        xT[(size_t)(n0 + r) * (CC / 8) + (c0 >> 3) + j] = val;
    }
}

// ---------------------------------------------------------------------------
// proj_qk (bf16 out) / proj_v (fp8 out)
// ---------------------------------------------------------------------------
__global__ __launch_bounds__(256)
void proj_qk_kernel(const float* __restrict__ scale, const float* __restrict__ bias,
                    int which)
{
    extern __shared__ __align__(1024) char smem[];
    const uint32_t sb = smem_u32(smem);
    const int tid = threadIdx.x;
    const int lane = tid & 31, wid = tid >> 5;
    const int wm = wid >> 2, wn = wid & 3;
    const int bz = blockIdx.z, n0 = blockIdx.x * 128;

    const uint4* Ag = (const uint4*)(g_xT + (size_t)bz * NN * CC);
    const uint4* Bg = (const uint4*)(which ? g_wkp : g_wqp);

    float acc[4][4][4];
#pragma unroll
    for (int i = 0; i < 4; i++)
#pragma unroll
        for (int j = 0; j < 4; j++)
#pragma unroll
            for (int k = 0; k < 4; k++) acc[i][j][k] = 0.f;

    gemm128x128<8>(sb, Ag, Bg, CC / 8, CC / 8, n0, 0, acc);

    __nv_bfloat16* qT = (which ? g_kT : g_qT) + (size_t)bz * NN * NP;
    const int g = lane >> 2, tg = lane & 3;
#pragma unroll
    for (int mt = 0; mt < 4; mt++) {
#pragma unroll
        for (int half = 0; half < 2; half++) {
            int row = n0 + wm * 64 + mt * 16 + g + half * 8;
#pragma unroll
            for (int nt = 0; nt < 4; nt++) {
                int c = wn * 32 + nt * 8 + tg * 2;
                float r0 = 0.f, r1 = 0.f;
                if (c < CQ) {
                    r0 = fmaf(acc[mt][nt][half * 2 + 0], scale[c], bias[c]);
                    r1 = fmaf(acc[mt][nt][half * 2 + 1], scale[c + 1], bias[c + 1]);
                    r0 = r0 > 0.f ? r0 : 0.f;
                    r1 = r1 > 0.f ? r1 : 0.f;
                }
                __nv_bfloat162 pk;
                pk.x = __float2bfloat16(r0);
                pk.y = __float2bfloat16(r1);
                *(__nv_bfloat162*)&qT[(size_t)row * NP + c] = pk;
            }
        }
    }
}

__global__ __launch_bounds__(256)
void proj_v_kernel(const float* __restrict__ scale, const float* __restrict__ bias)
{
    extern __shared__ __align__(1024) char smem[];
    const uint32_t sb = smem_u32(smem);
    const int tid = threadIdx.x;
    const int lane = tid & 31, wid = tid >> 5;
    const int wm = wid >> 2, wn = wid & 3;
    const int bz = blockIdx.z, c0 = blockIdx.x * 128, n0 = blockIdx.y * 128;

    const uint4* Ag = (const uint4*)g_wv;
    const uint4* Bg = (const uint4*)(g_xT + (size_t)bz * NN * CC);

    float acc[4][4][4];
#pragma unroll
    for (int i = 0; i < 4; i++)
#pragma unroll
        for (int j = 0; j < 4; j++)
#pragma unroll
            for (int k = 0; k < 4; k++) acc[i][j][k] = 0.f;

    gemm128x128<8>(sb, Ag, Bg, CC / 8, CC / 8, c0, n0, acc);

    unsigned char* Yb = g_v8 + (size_t)bz * CC * NN;
    const int g = lane >> 2, tg = lane & 3;
#pragma unroll
    for (int mt = 0; mt < 4; mt++) {
#pragma unroll
        for (int half = 0; half < 2; half++) {
            int c = c0 + wm * 64 + mt * 16 + g + half * 8;
            float s = scale[c], bi = bias[c];
#pragma unroll
            for (int nt = 0; nt < 4; nt++) {
                int n = n0 + wn * 32 + nt * 8 + tg * 2;
                float r0 = fmaf(acc[mt][nt][half * 2 + 0], s, bi);
                float r1 = fmaf(acc[mt][nt][half * 2 + 1], s, bi);
                r0 = r0 > 0.f ? r0 : 0.f;
                r1 = r1 > 0.f ? r1 : 0.f;
                float d0, d1;
                uint16_t pk = pack_fp8x2(r0, r1, d0, d1);
                *(uint16_t*)&Yb[(size_t)c * NN + n] = pk;
            }
        }
    }
}

// ---------------------------------------------------------------------------
// energy_p: P[i,j] = exp(q_i·k_j) -> bf16 g_attnb (coalesced via smem stage);
// per-row max of P -> g_pmax_bits via atomicMax (P > 0 so uint order works).
// No offset needed: E <= ~36 so exp fits float/bf16; softmax normalization
// comes from lsum over stored values (computed in convert_p).
// ---------------------------------------------------------------------------
__global__ __launch_bounds__(256)
void energy_p_kernel()
{
    extern __shared__ __align__(1024) char smem[];
    const uint32_t sb = smem_u32(smem);
    const int tid = threadIdx.x;
    const int lane = tid & 31, wid = tid >> 5;
    const int wm = wid >> 2, wn = wid & 3;
    const int bz = blockIdx.z, i0 = blockIdx.x * 128, j0 = blockIdx.y * 128;

    const uint4* qa = (const uint4*)(g_qT + (size_t)bz * NN * NP);
    const uint4* ka = (const uint4*)(g_kT + (size_t)bz * NN * NP);

    float acc[4][4][4];
#pragma unroll
    for (int i = 0; i < 4; i++)
#pragma unroll
        for (int j = 0; j < 4; j++)
#pragma unroll
            for (int k = 0; k < 4; k++) acc[i][j][k] = 0.f;

    gemm128x128<2>(sb, qa, ka, NP / 8, NP / 8, i0, j0, acc);

    unsigned* pmax = g_pmax_bits + (size_t)bz * NN;
    __nv_bfloat16* attn = g_attnb + (size_t)bz * NN * NN;

    const int g = lane >> 2, tg = lane & 3;

#pragma unroll
    for (int mt = 0; mt < 4; mt++) {
        const int r0l = wm * 64 + mt * 16 + g;
        const int r1l = r0l + 8;
        const int m0r = i0 + r0l;
        float m0 = 0.f, m1 = 0.f;
#pragma unroll
        for (int nt = 0; nt < 4; nt++) {
            int jl = wn * 32 + nt * 8 + tg * 2;
            float p00 = __expf(acc[mt][nt][0]);
            float p01 = __expf(acc[mt][nt][1]);
            float p10 = __expf(acc[mt][nt][2]);
            float p11 = __expf(acc[mt][nt][3]);
            m0 = fmaxf(m0, fmaxf(p00, p01));
            m1 = fmaxf(m1, fmaxf(p10, p11));
            __nv_bfloat162 pk0 = __float22bfloat162_rn(make_float2(p00, p01));
            __nv_bfloat162 pk1 = __float22bfloat162_rn(make_float2(p10, p11));
            uint32_t a0 = sb + r0l * 256 + (((jl >> 3) ^ (r0l & 7)) * 16) + ((jl * 2) & 15);
            uint32_t a1 = sb + r1l * 256 + (((jl >> 3) ^ (r1l & 7)) * 16) + ((jl * 2) & 15);
            asm volatile("st.shared.b32 [%0], %1;" :: "r"(a0), "r"(*(uint32_t*)&pk0) : "memory");
            asm volatile("st.shared.b32 [%0], %1;" :: "r"(a1), "r"(*(uint32_t*)&pk1) : "memory");
        }
        m0 = fmaxf(m0, __shfl_xor_sync(0xffffffffu, m0, 1));
        m0 = fmaxf(m0, __shfl_xor_sync(0xffffffffu, m0, 2));
        m1 = fmaxf(m1, __shfl_xor_sync(0xffffffffu, m1, 1));
        m1 = fmaxf(m1, __shfl_xor_sync(0xffffffffu, m1, 2));
        if (tg == 0) {
            atomicMax(&pmax[m0r], __float_as_uint(m0));
            atomicMax(&pmax[m0r + 8], __float_as_uint(m1));
        }
    }
    __syncthreads();

    // coalesced copy: 128 rows x 256B = 2048 uint4
#pragma unroll
    for (int p = 0; p < 8; p++) {
        int idx = p * 256 + tid;
        int r = idx >> 4, ch = idx & 15;
        uint4 val = *(uint4*)(smem + r * 256 + ((ch ^ (r & 7)) * 16));
        *(uint4*)&attn[(size_t)(i0 + r) * NN + j0 + ch * 8] = val;
    }
}

// ---------------------------------------------------------------------------
// convert_p: one block per row. P8 = fp8(P * 192/pmax_row); lsum = sum of
// dequantized stored values (exact normalization downstream; scale cancels).
// ---------------------------------------------------------------------------
__global__ __launch_bounds__(256)
void convert_p_kernel()
{
    __shared__ float red[8];
    const size_t row = blockIdx.x;                 // 0 .. BB*NN-1
    const __nv_bfloat16* src = g_attnb + row * NN;
    unsigned char* dst = g_attn8 + row * NN;
    const int tid = threadIdx.x;
    const int lane = tid & 31, wid = tid >> 5;

    const float scale = 192.f / __uint_as_float(g_pmax_bits[row]);

    float sum = 0.f;
#pragma unroll
    for (int it = 0; it < 2; it++) {
        int e = (it * 256 + tid) * 8;              // element index (8 per thread)
        uint4 v = *(const uint4*)&src[e];
        const uint32_t* w = (const uint32_t*)&v;
        uint16_t pk[4];
#pragma unroll
        for (int u = 0; u < 4; u++) {
            float2 f = __bfloat1622float2(*(const __nv_bfloat162*)&w[u]);
            float qa, qb;
            pk[u] = pack_fp8x2(f.x * scale, f.y * scale, qa, qb);
            sum += qa + qb;
        }
        *(uint2*)&dst[e] = *(uint2*)pk;
    }

    // block reduce
#pragma unroll
    for (int off = 16; off > 0; off >>= 1)
        sum += __shfl_xor_sync(0xffffffffu, sum, off);
    if (lane == 0) red[wid] = sum;
    __syncthreads();
    if (tid == 0) {
        float s = 0.f;
#pragma unroll
        for (int i = 0; i < 8; i++) s += red[i];
        g_lsum[row] = s;
    }
}

// ---------------------------------------------------------------------------
// out (fp8): O[c,i] = (sum_j v8[c,j]*P8[i,j]) / lsum[i];  out = gamma*O + x.
// CTA 128x128, warp 64x32. BK=128 fp8 (128B rows), 3-stage pipeline (96KB).
// m16n8k32 e4m3; ldmatrix.b16 on fp8 k-major tiles (2 fp8 per b16 element).
// ---------------------------------------------------------------------------
__global__ void __launch_bounds__(256)
out_kernel(const float* __restrict__ gamma, const float* __restrict__ x,
           float* __restrict__ out)
{
    extern __shared__ __align__(1024) char smem[];
    const uint32_t sb = smem_u32(smem);
    const int tid = threadIdx.x;
    const int lane = tid & 31, wid = tid >> 5;
    const int wm = wid >> 2, wn = wid & 3;
    const int bz = blockIdx.z, c0 = blockIdx.x * 128, i0 = blockIdx.y * 128;
    const int lr = tid >> 3, lc = tid & 7;

    const unsigned char* va = g_v8    + (size_t)bz * CC * NN;
    const unsigned char* aa = g_attn8 + (size_t)bz * NN * NN;

    int a_r[4], b_r[2];
#pragma unroll
    for (int mt = 0; mt < 4; mt++) a_r[mt] = wm * 64 + mt * 16 + ((lane >> 3) & 1) * 8 + (lane & 7);
#pragma unroll
    for (int p = 0; p < 2; p++) b_r[p] = wn * 32 + p * 16 + ((lane >> 4) & 1) * 8 + (lane & 7);
    const int a_kc = (lane >> 4) & 1;
    const int b_kc = (lane >> 3) & 1;

    float acc[4][4][4];
#pragma unroll
    for (int i = 0; i < 4; i++)
#pragma unroll
        for (int j = 0; j < 4; j++)
#pragma unroll
            for (int k = 0; k < 4; k++) acc[i][j][k] = 0.f;

    // prologue: tiles 0, 1 (each: A 16KB + B 16KB, stage stride 32768)
#pragma unroll
    for (int st = 0; st < 2; st++) {
        uint32_t dA = sb + (uint32_t)st * 32768, dB = dA + 16384;
#pragma unroll
        for (int p = 0; p < 4; p++) {
            int r = p * 32 + lr;
            CP_ASYNC16(dA + SW(r, lc), (const void*)(va + (size_t)(c0 + r) * NN + st * 128 + lc * 16));
            CP_ASYNC16(dB + SW(r, lc), (const void*)(aa + (size_t)(i0 + r) * NN + st * 128 + lc * 16));
        }
        CP_COMMIT();
    }

    int buf = 0, nbuf = 1;
#pragma unroll 1
    for (int t = 0; t < 32; t++) {
        if (t + 1 < 32) CP_WAIT1(); else CP_WAIT0();
        __syncthreads();

        if (t + 2 < 32) {
            int pb = (nbuf + 1 == 3) ? 0 : nbuf + 1;
            uint32_t dA = sb + (uint32_t)pb * 32768, dB = dA + 16384;
#pragma unroll
            for (int p = 0; p < 4; p++) {
                int r = p * 32 + lr;
                CP_ASYNC16(dA + SW(r, lc),
                           (const void*)(va + (size_t)(c0 + r) * NN + (t + 2) * 128 + lc * 16));
                CP_ASYNC16(dB + SW(r, lc),
                           (const void*)(aa + (size_t)(i0 + r) * NN + (t + 2) * 128 + lc * 16));
            }
            CP_COMMIT();
        }

        const uint32_t Asb = sb + (uint32_t)buf * 32768;
        const uint32_t Bsb = Asb + 16384;
#pragma unroll
        for (int ks = 0; ks < 4; ks++) {   // 4 k-steps of 32 fp8 each
            uint32_t aF[4][4], bF[2][4];
#pragma unroll
            for (int mt = 0; mt < 4; mt++)
                ldsm4(aF[mt][0], aF[mt][1], aF[mt][2], aF[mt][3],
                      Asb + SW(a_r[mt], ks * 2 + a_kc));
#pragma unroll
            for (int p = 0; p < 2; p++)
                ldsm4(bF[p][0], bF[p][1], bF[p][2], bF[p][3],
                      Bsb + SW(b_r[p], ks * 2 + b_kc));
#pragma unroll
            for (int mt = 0; mt < 4; mt++) {
                mma16832fp8(acc[mt][0], aF[mt][0], aF[mt][1], aF[mt][2], aF[mt][3], bF[0][0], bF[0][1]);
                mma16832fp8(acc[mt][1], aF[mt][0], aF[mt][1], aF[mt][2], aF[mt][3], bF[0][2], bF[0][3]);
                mma16832fp8(acc[mt][2], aF[mt][0], aF[mt][1], aF[mt][2], aF[mt][3], bF[1][0], bF[1][1]);
                mma16832fp8(acc[mt][3], aF[mt][0], aF[mt][1], aF[mt][2], aF[mt][3], bF[1][2], bF[1][3]);
            }
        }
        buf = (buf + 1 == 3) ? 0 : buf + 1;
        nbuf = (nbuf + 1 == 3) ? 0 : nbuf + 1;
    }

    const float* lsum = g_lsum + (size_t)bz * NN;
    const int g = lane >> 2, tg = lane & 3;

    float li[4][2];
#pragma unroll
    for (int nt = 0; nt < 4; nt++) {
        int n = i0 + wn * 32 + nt * 8 + tg * 2;
        li[nt][0] = 1.f / lsum[n];
        li[nt][1] = 1.f / lsum[n + 1];
    }

#pragma unroll
    for (int mt = 0; mt < 4; mt++) {
#pragma unroll
        for (int half = 0; half < 2; half++) {
            int c = c0 + wm * 64 + mt * 16 + g + half * 8;
#pragma unroll
            for (int nt = 0; nt < 4; nt++) {
                int n = i0 + wn * 32 + nt * 8 + tg * 2;
                size_t gi = (size_t)c * NN + n;
                size_t bi = (size_t)bz * CC * NN + gi;
                float2 gm = *(const float2*)&gamma[gi];
                float2 xx = *(const float2*)&x[bi];
                float2 o;
                o.x = fmaf(gm.x, acc[mt][nt][half * 2 + 0] * li[nt][0], xx.x);
                o.y = fmaf(gm.y, acc[mt][nt][half * 2 + 1] * li[nt][1], xx.y);
                *(float2*)&out[bi] = o;
            }
        }
    }
}

// ---------------------------------------------------------------------------
extern "C" void kernel_launch(void* const* d_in, const int* in_sizes, int n_in,
                              void* d_out, int out_size)
{
    const float* x     = (const float*)d_in[0];
    const float* Wq    = (const float*)d_in[1];
    const float* Wk    = (const float*)d_in[2];
    const float* Wv    = (const float*)d_in[3];
    const float* sq    = (const float*)d_in[4];
    const float* bq    = (const float*)d_in[5];
    const float* sk    = (const float*)d_in[6];
    const float* bk    = (const float*)d_in[7];
    const float* sv    = (const float*)d_in[8];
    const float* bv    = (const float*)d_in[9];
    const float* gamma = (const float*)d_in[10];
    float* out = (float*)d_out;

    const int DSMEM = 98304;
    cudaFuncSetAttribute(proj_qk_kernel,  cudaFuncAttributeMaxDynamicSharedMemorySize, DSMEM);
    cudaFuncSetAttribute(proj_v_kernel,   cudaFuncAttributeMaxDynamicSharedMemorySize, DSMEM);
    cudaFuncSetAttribute(energy_p_kernel, cudaFuncAttributeMaxDynamicSharedMemorySize, DSMEM);
    cudaFuncSetAttribute(out_kernel,      cudaFuncAttributeMaxDynamicSharedMemorySize, DSMEM);

    dim3 blk(256);

    convert_w_kernel<<<(CC * CC + 2 * NP * CC) / 256, blk>>>(Wv, Wq, Wk);
    transpose_x_kernel<<<dim3(CC / 128, NN / 128, BB), blk>>>(x);

    proj_qk_kernel<<<dim3(NN / 128, 1, BB), blk, DSMEM>>>(sq, bq, 0);
    proj_qk_kernel<<<dim3(NN / 128, 1, BB), blk, DSMEM>>>(sk, bk, 1);

    proj_v_kernel<<<dim3(CC / 128, NN / 128, BB), blk, DSMEM>>>(sv, bv);

    energy_p_kernel<<<dim3(NN / 128, NN / 128, BB), blk, DSMEM>>>();

    convert_p_kernel<<<BB * NN, blk>>>();

    out_kernel<<<dim3(CC / 128, NN / 128, BB), blk, DSMEM>>>(gamma, x, out);
}

// round 13
// speedup vs baseline: 1.1795x; 1.1795x over previous
#include <cuda_runtime.h>
#include <cuda_bf16.h>
#include <cstdint>

#define BB 8
#define CC 512
#define NN 4096
#define CQ 80
#define NP 128   // CQ padded to 128 for bf16 MMA K

// ---------------- scratch (device globals; allocation-guard safe) ----------
__device__ __nv_bfloat16  g_attnb [(size_t)BB * NN * NN];   // 256 MB bf16 (unnormalized P)
__device__ float          g_lsum  [(size_t)BB * NN];        // row sums of P
__device__ float          g_qnorm [(size_t)BB * NN];        // ||q_i||_2
__device__ unsigned       g_kmax_bits[BB];                  // max_j ||k_j||_2 (float bits)
__device__ __nv_bfloat16  g_vb    [(size_t)BB * CC * NN];   // 64 MB  [b][c][n]
__device__ __nv_bfloat16  g_qT    [(size_t)BB * NN * NP];   // 8 MB   [b][n][c] padded
__device__ __nv_bfloat16  g_kT    [(size_t)BB * NN * NP];
__device__ __nv_bfloat16  g_xT    [(size_t)BB * NN * CC];   // 33.5 MB [b][n][c]
__device__ __nv_bfloat16  g_wv    [(size_t)CC * CC];
__device__ __nv_bfloat16  g_wqp   [(size_t)NP * CC];
__device__ __nv_bfloat16  g_wkp   [(size_t)NP * CC];

// ---------------- helpers ---------------------------------------------------
__device__ __forceinline__ uint32_t smem_u32(const void* p) {
    uint32_t a;
    asm("{ .reg .u64 t; cvta.to.shared.u64 t, %1; cvt.u32.u64 %0, t; }" : "=r"(a) : "l"(p));
    return a;
}
__device__ __forceinline__ void ldsm4(uint32_t& r0, uint32_t& r1, uint32_t& r2, uint32_t& r3,
                                      uint32_t addr) {
    asm volatile("ldmatrix.sync.aligned.m8n8.x4.shared.b16 {%0,%1,%2,%3}, [%4];"
                 : "=r"(r0), "=r"(r1), "=r"(r2), "=r"(r3) : "r"(addr));
}
__device__ __forceinline__ void mma16816(float* c, uint32_t a0, uint32_t a1, uint32_t a2,
                                         uint32_t a3, uint32_t b0, uint32_t b1) {
    asm volatile("mma.sync.aligned.m16n8k16.row.col.f32.bf16.bf16.f32 "
                 "{%0,%1,%2,%3},{%4,%5,%6,%7},{%8,%9},{%0,%1,%2,%3};"
                 : "+f"(c[0]), "+f"(c[1]), "+f"(c[2]), "+f"(c[3])
                 : "r"(a0), "r"(a1), "r"(a2), "r"(a3), "r"(b0), "r"(b1));
}
#define CP_ASYNC16(dst, src) \
    asm volatile("cp.async.cg.shared.global [%0], [%1], 16;" :: "r"(dst), "l"(src))
#define CP_COMMIT() asm volatile("cp.async.commit_group;" ::: "memory")
#define CP_WAIT1()  asm volatile("cp.async.wait_group 1;" ::: "memory")
#define CP_WAIT0()  asm volatile("cp.async.wait_group 0;" ::: "memory")

// 128B-row (64 bf16) swizzle; chunk in [0,8)
#define SW(r, c) ((uint32_t)(((r) * 128) + ((((c) ^ ((r) & 7))) * 16)))

// ---------------------------------------------------------------------------
// 128x128 bf16 GEMM body (R8-proven, 2-stage double buffer).
// ---------------------------------------------------------------------------
template <int NK>
__device__ __forceinline__ void gemm128x128(uint32_t sb, const uint4* __restrict__ Ag,
                                            const uint4* __restrict__ Bg, int aStride,
                                            int bStride, int m0, int n0,
                                            float (&acc)[4][4][4]) {
    const int tid = threadIdx.x;
    const int lane = tid & 31, wid = tid >> 5;
    const int wm = wid >> 2, wn = wid & 3;
    const int lr = tid >> 3, lc = tid & 7;

    int a_r[4], b_r[2];
#pragma unroll
    for (int mt = 0; mt < 4; mt++) a_r[mt] = wm * 64 + mt * 16 + ((lane >> 3) & 1) * 8 + (lane & 7);
#pragma unroll
    for (int p = 0; p < 2; p++) b_r[p] = wn * 32 + p * 16 + ((lane >> 4) & 1) * 8 + (lane & 7);
    const int a_kc = (lane >> 4) & 1;
    const int b_kc = (lane >> 3) & 1;

    {
        uint32_t dA = sb, dB = sb + 16384;
#pragma unroll
        for (int p = 0; p < 4; p++) {
            int r = p * 32 + lr;
            CP_ASYNC16(dA + SW(r, lc), (const void*)(Ag + (size_t)(m0 + r) * aStride + lc));
            CP_ASYNC16(dB + SW(r, lc), (const void*)(Bg + (size_t)(n0 + r) * bStride + lc));
        }
        CP_COMMIT();
    }

#pragma unroll 1
    for (int t = 0; t < NK; t++) {
        if (t + 1 < NK) {
            uint32_t dA = sb + ((t + 1) & 1) * 32768, dB = dA + 16384;
#pragma unroll
            for (int p = 0; p < 4; p++) {
                int r = p * 32 + lr;
                CP_ASYNC16(dA + SW(r, lc),
                           (const void*)(Ag + (size_t)(m0 + r) * aStride + (t + 1) * 8 + lc));
                CP_ASYNC16(dB + SW(r, lc),
                           (const void*)(Bg + (size_t)(n0 + r) * bStride + (t + 1) * 8 + lc));
            }
            CP_COMMIT();
            CP_WAIT1();
        } else {
            CP_WAIT0();
        }
        __syncthreads();

        const uint32_t Asb = sb + (t & 1) * 32768;
        const uint32_t Bsb = Asb + 16384;
#pragma unroll
        for (int ks = 0; ks < 4; ks++) {
            uint32_t aF[4][4], bF[2][4];
#pragma unroll
            for (int mt = 0; mt < 4; mt++)
                ldsm4(aF[mt][0], aF[mt][1], aF[mt][2], aF[mt][3],
                      Asb + SW(a_r[mt], ks * 2 + a_kc));
#pragma unroll
            for (int p = 0; p < 2; p++)
                ldsm4(bF[p][0], bF[p][1], bF[p][2], bF[p][3],
                      Bsb + SW(b_r[p], ks * 2 + b_kc));
#pragma unroll
            for (int mt = 0; mt < 4; mt++) {
                mma16816(acc[mt][0], aF[mt][0], aF[mt][1], aF[mt][2], aF[mt][3], bF[0][0], bF[0][1]);
                mma16816(acc[mt][1], aF[mt][0], aF[mt][1], aF[mt][2], aF[mt][3], bF[0][2], bF[0][3]);
                mma16816(acc[mt][2], aF[mt][0], aF[mt][1], aF[mt][2], aF[mt][3], bF[1][0], bF[1][1]);
                mma16816(acc[mt][3], aF[mt][0], aF[mt][1], aF[mt][2], aF[mt][3], bF[1][2], bF[1][3]);
            }
        }
        __syncthreads();
    }
}

// ---------------------------------------------------------------------------
// convert_w (+ zero g_lsum / g_kmax_bits)
// ---------------------------------------------------------------------------
__global__ __launch_bounds__(256)
void convert_w_kernel(const float* __restrict__ Wv, const float* __restrict__ Wq,
                      const float* __restrict__ Wk)
{
    int idx = blockIdx.x * 256 + threadIdx.x;
    if (idx < BB * NN) g_lsum[idx] = 0.f;
    if (idx < BB) g_kmax_bits[idx] = 0u;
    if (idx < CC * CC) {
        g_wv[idx] = __float2bfloat16(Wv[idx]);
    } else if (idx < CC * CC + NP * CC) {
        int i = idx - CC * CC;
        int row = i >> 9, col = i & 511;
        g_wqp[i] = __float2bfloat16(row < CQ ? Wq[row * CC + col] : 0.f);
    } else {
        int i = idx - CC * CC - NP * CC;
        int row = i >> 9, col = i & 511;
        g_wkp[i] = __float2bfloat16(row < CQ ? Wk[row * CC + col] : 0.f);
    }
}

// ---------------------------------------------------------------------------
// transpose_x: x [b][c][n] fp32 -> xT [b][n][c] bf16.
// ---------------------------------------------------------------------------
__global__ __launch_bounds__(256)
void transpose_x_kernel(const float* __restrict__ x)
{
    __shared__ __nv_bfloat16 st[128][136];
    const int b  = blockIdx.z;
    const int c0 = blockIdx.x * 128;
    const int n0 = blockIdx.y * 128;
    const int tid = threadIdx.x;

    const float* xb = x + (size_t)b * CC * NN;
#pragma unroll
    for (int k = 0; k < 8; k++) {
        int row = k * 16 + (tid >> 4);
        int col = (tid & 15) * 8;
        const float* p = xb + (size_t)(c0 + row) * NN + n0 + col;
        float4 v0 = *(const float4*)p;
        float4 v1 = *(const float4*)(p + 4);
        st[col + 0][row] = __float2bfloat16(v0.x);
        st[col + 1][row] = __float2bfloat16(v0.y);
        st[col + 2][row] = __float2bfloat16(v0.z);
        st[col + 3][row] = __float2bfloat16(v0.w);
        st[col + 4][row] = __float2bfloat16(v1.x);
        st[col + 5][row] = __float2bfloat16(v1.y);
        st[col + 6][row] = __float2bfloat16(v1.z);
        st[col + 7][row] = __float2bfloat16(v1.w);
    }
    __syncthreads();

    uint4* xT = (uint4*)(g_xT + (size_t)b * NN * CC);
#pragma unroll
    for (int k = 0; k < 8; k++) {
        int idx = k * 256 + tid;
        int r = idx >> 4, j = idx & 15;
        uint4 val = *(uint4*)&st[r][j * 8];
        xT[(size_t)(n0 + r) * (CC / 8) + (c0 >> 3) + j] = val;
    }
}

// ---------------------------------------------------------------------------
// proj_qk / proj_v (R8-proven)
// ---------------------------------------------------------------------------
__global__ __launch_bounds__(256)
void proj_qk_kernel(const float* __restrict__ scale, const float* __restrict__ bias,
                    int which)
{
    extern __shared__ __align__(1024) char smem[];
    const uint32_t sb = smem_u32(smem);
    const int tid = threadIdx.x;
    const int lane = tid & 31, wid = tid >> 5;
    const int wm = wid >> 2, wn = wid & 3;
    const int bz = blockIdx.z, n0 = blockIdx.x * 128;

    const uint4* Ag = (const uint4*)(g_xT + (size_t)bz * NN * CC);
    const uint4* Bg = (const uint4*)(which ? g_wkp : g_wqp);

    float acc[4][4][4];
#pragma unroll
    for (int i = 0; i < 4; i++)
#pragma unroll
        for (int j = 0; j < 4; j++)
#pragma unroll
            for (int k = 0; k < 4; k++) acc[i][j][k] = 0.f;

    gemm128x128<8>(sb, Ag, Bg, CC / 8, CC / 8, n0, 0, acc);

    __nv_bfloat16* qT = (which ? g_kT : g_qT) + (size_t)bz * NN * NP;
    const int g = lane >> 2, tg = lane & 3;
#pragma unroll
    for (int mt = 0; mt < 4; mt++) {
#pragma unroll
        for (int half = 0; half < 2; half++) {
            int row = n0 + wm * 64 + mt * 16 + g + half * 8;
#pragma unroll
            for (int nt = 0; nt < 4; nt++) {
                int c = wn * 32 + nt * 8 + tg * 2;
                float r0 = 0.f, r1 = 0.f;
                if (c < CQ) {
                    r0 = fmaf(acc[mt][nt][half * 2 + 0], scale[c], bias[c]);
                    r1 = fmaf(acc[mt][nt][half * 2 + 1], scale[c + 1], bias[c + 1]);
                    r0 = r0 > 0.f ? r0 : 0.f;
                    r1 = r1 > 0.f ? r1 : 0.f;
                }
                __nv_bfloat162 pk;
                pk.x = __float2bfloat16(r0);
                pk.y = __float2bfloat16(r1);
                *(__nv_bfloat162*)&qT[(size_t)row * NP + c] = pk;
            }
        }
    }
}

__global__ __launch_bounds__(256)
void proj_v_kernel(const float* __restrict__ scale, const float* __restrict__ bias)
{
    extern __shared__ __align__(1024) char smem[];
    const uint32_t sb = smem_u32(smem);
    const int tid = threadIdx.x;
    const int lane = tid & 31, wid = tid >> 5;
    const int wm = wid >> 2, wn = wid & 3;
    const int bz = blockIdx.z, c0 = blockIdx.x * 128, n0 = blockIdx.y * 128;

    const uint4* Ag = (const uint4*)g_wv;
    const uint4* Bg = (const uint4*)(g_xT + (size_t)bz * NN * CC);

    float acc[4][4][4];
#pragma unroll
    for (int i = 0; i < 4; i++)
#pragma unroll
        for (int j = 0; j < 4; j++)
#pragma unroll
            for (int k = 0; k < 4; k++) acc[i][j][k] = 0.f;

    gemm128x128<8>(sb, Ag, Bg, CC / 8, CC / 8, c0, n0, acc);

    __nv_bfloat16* Yb = g_vb + (size_t)bz * CC * NN;
    const int g = lane >> 2, tg = lane & 3;
#pragma unroll
    for (int mt = 0; mt < 4; mt++) {
#pragma unroll
        for (int half = 0; half < 2; half++) {
            int c = c0 + wm * 64 + mt * 16 + g + half * 8;
            float s = scale[c], bi = bias[c];
#pragma unroll
            for (int nt = 0; nt < 4; nt++) {
                int n = n0 + wn * 32 + nt * 8 + tg * 2;
                float r0 = fmaf(acc[mt][nt][half * 2 + 0], s, bi);
                float r1 = fmaf(acc[mt][nt][half * 2 + 1], s, bi);
                __nv_bfloat162 pk;
                pk.x = __float2bfloat16(r0 > 0.f ? r0 : 0.f);
                pk.y = __float2bfloat16(r1 > 0.f ? r1 : 0.f);
                *(__nv_bfloat162*)&Yb[(size_t)c * NN + n] = pk;
            }
        }
    }
}

// ---------------------------------------------------------------------------
// qk_norms (R8-proven)
// ---------------------------------------------------------------------------
__global__ __launch_bounds__(256)
void qk_norms_kernel()
{
    const int row = blockIdx.x * 256 + threadIdx.x;
    const int b = row >> 12;

    const uint4* qr = (const uint4*)(g_qT + (size_t)row * NP);
    const uint4* kr = (const uint4*)(g_kT + (size_t)row * NP);
    float qs = 0.f, ks = 0.f;
#pragma unroll
    for (int j = 0; j < 16; j++) {
        uint4 qv = qr[j], kv = kr[j];
        const uint32_t* qw = (const uint32_t*)&qv;
        const uint32_t* kw = (const uint32_t*)&kv;
#pragma unroll
        for (int w = 0; w < 4; w++) {
            float2 qf = __bfloat1622float2(*(const __nv_bfloat162*)&qw[w]);
            float2 kf = __bfloat1622float2(*(const __nv_bfloat162*)&kw[w]);
            qs = fmaf(qf.x, qf.x, qs); qs = fmaf(qf.y, qf.y, qs);
            ks = fmaf(kf.x, kf.x, ks); ks = fmaf(kf.y, kf.y, ks);
        }
    }
    g_qnorm[row] = sqrtf(qs);
    float kn = sqrtf(ks);
    atomicMax(&g_kmax_bits[b], __float_as_uint(kn));
}

// ---------------------------------------------------------------------------
// energy_p (R8-proven): P[i,j] = exp(q_i·k_j - bound_i) -> bf16 g_attnb,
// partial row sums atomicAdd into g_lsum. bound_i = ||q_i|| * max||k||.
// ---------------------------------------------------------------------------
__global__ __launch_bounds__(256)
void energy_p_kernel()
{
    extern __shared__ __align__(1024) char smem[];
    const uint32_t sb = smem_u32(smem);
    const int tid = threadIdx.x;
    const int lane = tid & 31, wid = tid >> 5;
    const int wm = wid >> 2, wn = wid & 3;
    const int bz = blockIdx.z, i0 = blockIdx.x * 128, j0 = blockIdx.y * 128;

    const uint4* qa = (const uint4*)(g_qT + (size_t)bz * NN * NP);
    const uint4* ka = (const uint4*)(g_kT + (size_t)bz * NN * NP);

    float acc[4][4][4];
#pragma unroll
    for (int i = 0; i < 4; i++)
#pragma unroll
        for (int j = 0; j < 4; j++)
#pragma unroll
            for (int k = 0; k < 4; k++) acc[i][j][k] = 0.f;

    gemm128x128<2>(sb, qa, ka, NP / 8, NP / 8, i0, j0, acc);

    const float kmax = __uint_as_float(g_kmax_bits[bz]);
    const float* qn = g_qnorm + (size_t)bz * NN;
    float* lsum = g_lsum + (size_t)bz * NN;
    __nv_bfloat16* attn = g_attnb + (size_t)bz * NN * NN;

    const int g = lane >> 2, tg = lane & 3;
#pragma unroll
    for (int mt = 0; mt < 4; mt++) {
        const int m0r = i0 + wm * 64 + mt * 16 + g;
        const float b0 = qn[m0r] * kmax;
        const float b1 = qn[m0r + 8] * kmax;
        float s0 = 0.f, s1 = 0.f;
#pragma unroll
        for (int nt = 0; nt < 4; nt++) {
            int n = j0 + wn * 32 + nt * 8 + tg * 2;
            float p00 = __expf(acc[mt][nt][0] - b0);
            float p01 = __expf(acc[mt][nt][1] - b0);
            float p10 = __expf(acc[mt][nt][2] - b1);
            float p11 = __expf(acc[mt][nt][3] - b1);
            s0 += p00 + p01;
            s1 += p10 + p11;
            __nv_bfloat162 pk0 = __float22bfloat162_rn(make_float2(p00, p01));
            __nv_bfloat162 pk1 = __float22bfloat162_rn(make_float2(p10, p11));
            *(__nv_bfloat162*)&attn[(size_t)m0r * NN + n]       = pk0;
            *(__nv_bfloat162*)&attn[(size_t)(m0r + 8) * NN + n] = pk1;
        }
        s0 += __shfl_xor_sync(0xffffffffu, s0, 1);
        s0 += __shfl_xor_sync(0xffffffffu, s0, 2);
        s1 += __shfl_xor_sync(0xffffffffu, s1, 1);
        s1 += __shfl_xor_sync(0xffffffffu, s1, 2);
        if (tg == 0) {
            atomicAdd(&lsum[m0r], s0);
            atomicAdd(&lsum[m0r + 8], s1);
        }
    }
}

// ---------------------------------------------------------------------------
// out v3: 128 threads (4 warps), CTA 128x128, WARP TILE 64x64, BK=64,
// double-buffered (64KB smem). 2 CTAs/SM (reg-limited), 2x mma per ldsm.
// O[c,i] = (sum_j v[c,j]*P[i,j]) / lsum[i];  out = gamma*O + x.
// ---------------------------------------------------------------------------
__global__ void __launch_bounds__(128)
out_kernel(const float* __restrict__ gamma, const float* __restrict__ x,
           float* __restrict__ out)
{
    extern __shared__ __align__(1024) char smem[];
    const uint32_t sb = smem_u32(smem);
    const int tid = threadIdx.x;
    const int lane = tid & 31, wid = tid >> 5;
    const int wm = wid >> 1, wn = wid & 1;
    const int bz = blockIdx.z, c0 = blockIdx.x * 128, i0 = blockIdx.y * 128;
    const int lr = tid >> 3, lc = tid & 7;   // lr 0..15, lc 0..7

    const uint4* va = (const uint4*)(g_vb    + (size_t)bz * CC * NN);   // 512 uint4/row
    const uint4* aa = (const uint4*)(g_attnb + (size_t)bz * NN * NN);

    int a_r[4], b_r[4];
#pragma unroll
    for (int mt = 0; mt < 4; mt++) a_r[mt] = wm * 64 + mt * 16 + ((lane >> 3) & 1) * 8 + (lane & 7);
#pragma unroll
    for (int p = 0; p < 4; p++) b_r[p] = wn * 64 + p * 16 + ((lane >> 4) & 1) * 8 + (lane & 7);
    const int a_kc = (lane >> 4) & 1;
    const int b_kc = (lane >> 3) & 1;

    float acc[4][8][4];
#pragma unroll
    for (int i = 0; i < 4; i++)
#pragma unroll
        for (int j = 0; j < 8; j++)
#pragma unroll
            for (int k = 0; k < 4; k++) acc[i][j][k] = 0.f;

    // prologue: tile 0 (A 128x64 + B 128x64; 128 threads -> 8 rows each)
    {
        uint32_t dA = sb, dB = sb + 16384;
#pragma unroll
        for (int p = 0; p < 8; p++) {
            int r = p * 16 + lr;
            CP_ASYNC16(dA + SW(r, lc), (const void*)(va + (size_t)(c0 + r) * 512 + lc));
            CP_ASYNC16(dB + SW(r, lc), (const void*)(aa + (size_t)(i0 + r) * 512 + lc));
        }
        CP_COMMIT();
    }

#pragma unroll 1
    for (int t = 0; t < 64; t++) {
        if (t + 1 < 64) {
            uint32_t dA = sb + ((t + 1) & 1) * 32768, dB = dA + 16384;
#pragma unroll
            for (int p = 0; p < 8; p++) {
                int r = p * 16 + lr;
                CP_ASYNC16(dA + SW(r, lc),
                           (const void*)(va + (size_t)(c0 + r) * 512 + (t + 1) * 8 + lc));
                CP_ASYNC16(dB + SW(r, lc),
                           (const void*)(aa + (size_t)(i0 + r) * 512 + (t + 1) * 8 + lc));
            }
            CP_COMMIT();
            CP_WAIT1();
        } else {
            CP_WAIT0();
        }
        __syncthreads();

        const uint32_t Asb = sb + (t & 1) * 32768;
        const uint32_t Bsb = Asb + 16384;
#pragma unroll
        for (int ks = 0; ks < 4; ks++) {
            uint32_t aF[4][4], bF[4][4];
#pragma unroll
            for (int mt = 0; mt < 4; mt++)
                ldsm4(aF[mt][0], aF[mt][1], aF[mt][2], aF[mt][3],
                      Asb + SW(a_r[mt], ks * 2 + a_kc));
#pragma unroll
            for (int p = 0; p < 4; p++)
                ldsm4(bF[p][0], bF[p][1], bF[p][2], bF[p][3],
                      Bsb + SW(b_r[p], ks * 2 + b_kc));
#pragma unroll
            for (int mt = 0; mt < 4; mt++)
#pragma unroll
                for (int p = 0; p < 4; p++) {
                    mma16816(acc[mt][p * 2 + 0], aF[mt][0], aF[mt][1], aF[mt][2], aF[mt][3],
                             bF[p][0], bF[p][1]);
                    mma16816(acc[mt][p * 2 + 1], aF[mt][0], aF[mt][1], aF[mt][2], aF[mt][3],
                             bF[p][2], bF[p][3]);
                }
        }
        __syncthreads();
    }

    const float* lsum = g_lsum + (size_t)bz * NN;
    const int g = lane >> 2, tg = lane & 3;

    float li[8][2];
#pragma unroll
    for (int nt = 0; nt < 8; nt++) {
        int n = i0 + wn * 64 + nt * 8 + tg * 2;
        li[nt][0] = 1.f / lsum[n];
        li[nt][1] = 1.f / lsum[n + 1];
    }

#pragma unroll
    for (int mt = 0; mt < 4; mt++) {
#pragma unroll
        for (int half = 0; half < 2; half++) {
            int c = c0 + wm * 64 + mt * 16 + g + half * 8;
#pragma unroll
            for (int nt = 0; nt < 8; nt++) {
                int n = i0 + wn * 64 + nt * 8 + tg * 2;
                size_t gi = (size_t)c * NN + n;
                size_t bi = (size_t)bz * CC * NN + gi;
                float2 gm = *(const float2*)&gamma[gi];
                float2 xx = *(const float2*)&x[bi];
                float2 o;
                o.x = fmaf(gm.x, acc[mt][nt][half * 2 + 0] * li[nt][0], xx.x);
                o.y = fmaf(gm.y, acc[mt][nt][half * 2 + 1] * li[nt][1], xx.y);
                *(float2*)&out[bi] = o;
            }
        }
    }
}

// ---------------------------------------------------------------------------
extern "C" void kernel_launch(void* const* d_in, const int* in_sizes, int n_in,
                              void* d_out, int out_size)
{
    const float* x     = (const float*)d_in[0];
    const float* Wq    = (const float*)d_in[1];
    const float* Wk    = (const float*)d_in[2];
    const float* Wv    = (const float*)d_in[3];
    const float* sq    = (const float*)d_in[4];
    const float* bq    = (const float*)d_in[5];
    const float* sk    = (const float*)d_in[6];
    const float* bk    = (const float*)d_in[7];
    const float* sv    = (const float*)d_in[8];
    const float* bv    = (const float*)d_in[9];
    const float* gamma = (const float*)d_in[10];
    float* out = (float*)d_out;

    const int DSMEM = 65536;
    cudaFuncSetAttribute(proj_qk_kernel,  cudaFuncAttributeMaxDynamicSharedMemorySize, DSMEM);
    cudaFuncSetAttribute(proj_v_kernel,   cudaFuncAttributeMaxDynamicSharedMemorySize, DSMEM);
    cudaFuncSetAttribute(energy_p_kernel, cudaFuncAttributeMaxDynamicSharedMemorySize, DSMEM);
    cudaFuncSetAttribute(out_kernel,      cudaFuncAttributeMaxDynamicSharedMemorySize, DSMEM);

    dim3 blk(256);

    convert_w_kernel<<<(CC * CC + 2 * NP * CC) / 256, blk>>>(Wv, Wq, Wk);
    transpose_x_kernel<<<dim3(CC / 128, NN / 128, BB), blk>>>(x);

    proj_qk_kernel<<<dim3(NN / 128, 1, BB), blk, DSMEM>>>(sq, bq, 0);
    proj_qk_kernel<<<dim3(NN / 128, 1, BB), blk, DSMEM>>>(sk, bk, 1);

    qk_norms_kernel<<<BB * NN / 256, blk>>>();

    proj_v_kernel<<<dim3(CC / 128, NN / 128, BB), blk, DSMEM>>>(sv, bv);

    energy_p_kernel<<<dim3(NN / 128, NN / 128, BB), blk, DSMEM>>>();

    out_kernel<<<dim3(CC / 128, NN / 128, BB), dim3(128), DSMEM>>>(gamma, x, out);
}